// round 1
// baseline (speedup 1.0000x reference)
#include <cuda_runtime.h>
#include <math.h>

#define THREADS 256

// One CTA processes 32 rows end-to-end. All intermediates live in SMEM.
// SMEM plan (floats):
//   buf  [32*768]  : x tile (32x512) -> ctx tile (32x768) -> y tile (32x512), reused
//   Qs   [32*128]  : softmaxed q
//   OUTs [32*128]  : s*v
//   s_sm [32*4], norm2[32], rsc[32]
__global__ void __launch_bounds__(THREADS, 1)
lca_fused(const float* __restrict__ x,   const float* __restrict__ ctx,
          const float* __restrict__ Wq,  const float* __restrict__ Wk,
          const float* __restrict__ Wv,  const float* __restrict__ Wo,
          const float* __restrict__ bo,  const float* __restrict__ g,
          float* __restrict__ out)
{
    extern __shared__ float smem[];
    float* buf   = smem;                 // 24576
    float* Qs    = buf  + 32 * 768;      // 4096
    float* OUTs  = Qs   + 32 * 128;      // 4096
    float* s_sm  = OUTs + 32 * 128;      // 128
    float* norm2 = s_sm + 128;           // 32
    float* rsc   = norm2 + 32;           // 32

    const int tid = threadIdx.x;
    const int tn  = tid & 31;            // 32 column-groups of 4 (covers N=128)
    const int tm  = tid >> 5;            // 8 row-groups of 4 (covers M=32)
    const int r0  = tm << 2;
    const int nb  = tn << 2;
    const int h   = tn >> 3;             // head of columns nb..nb+3
    const size_t Rbase = (size_t)blockIdx.x * 32;

    // ---------------- load x tile [32,512] ----------------
    {
        const float4* __restrict__ xg = (const float4*)(x + Rbase * 512);
        float4* xs = (float4*)buf;
        for (int i = tid; i < 32 * 128; i += THREADS) xs[i] = xg[i];
    }
    __syncthreads();

    // ---------------- Phase A: q = x @ Wq ----------------
    {
        float acc[4][4];
        #pragma unroll
        for (int mi = 0; mi < 4; mi++)
            #pragma unroll
            for (int ci = 0; ci < 4; ci++) acc[mi][ci] = 0.f;

        #pragma unroll 2
        for (int k0 = 0; k0 < 512; k0 += 4) {
            float a[4][4];
            #pragma unroll
            for (int mi = 0; mi < 4; mi++) {
                float4 t = *(const float4*)&buf[(r0 + mi) * 512 + k0];
                a[mi][0] = t.x; a[mi][1] = t.y; a[mi][2] = t.z; a[mi][3] = t.w;
            }
            #pragma unroll
            for (int kk = 0; kk < 4; kk++) {
                float4 b = __ldg((const float4*)&Wq[(k0 + kk) * 128 + nb]);
                #pragma unroll
                for (int mi = 0; mi < 4; mi++) {
                    float am = a[mi][kk];
                    acc[mi][0] = fmaf(am, b.x, acc[mi][0]);
                    acc[mi][1] = fmaf(am, b.y, acc[mi][1]);
                    acc[mi][2] = fmaf(am, b.z, acc[mi][2]);
                    acc[mi][3] = fmaf(am, b.w, acc[mi][3]);
                }
            }
        }
        #pragma unroll
        for (int mi = 0; mi < 4; mi++) {
            float4 t;
            t.x = acc[mi][0]; t.y = acc[mi][1]; t.z = acc[mi][2]; t.w = acc[mi][3];
            *(float4*)&Qs[(r0 + mi) * 128 + nb] = t;
        }
    }
    __syncthreads();  // Qs raw done; x in buf now dead

    // ---------- softmax per (row, head) in place (*scale), overlap ctx load ----------
    if (tid < 128) {
        const int m = tid >> 2, hh = tid & 3;
        float* qp = &Qs[m * 128 + hh * 32];
        float mx = qp[0];
        #pragma unroll
        for (int i = 1; i < 32; i++) mx = fmaxf(mx, qp[i]);
        float sum = 0.f;
        #pragma unroll
        for (int i = 0; i < 32; i++) sum += __expf(qp[i] - mx);
        const float inv = 0.17677669529663687f / sum;  // 32^-0.5 / sum
        #pragma unroll
        for (int i = 0; i < 32; i++) qp[i] = __expf(qp[i] - mx) * inv;
    }
    // load ctx tile [32,768] (all threads)
    {
        const float4* __restrict__ cg = (const float4*)(ctx + Rbase * 768);
        float4* cs = (float4*)buf;
        for (int i = tid; i < 32 * 192; i += THREADS) cs[i] = cg[i];
    }
    __syncthreads();

    // -------- Phase B: k = sigmoid(ctx@Wk), v = ctx@Wv, s = k.q, OUT = s*v --------
    {
        float ak[4][4], av[4][4];
        #pragma unroll
        for (int mi = 0; mi < 4; mi++)
            #pragma unroll
            for (int ci = 0; ci < 4; ci++) { ak[mi][ci] = 0.f; av[mi][ci] = 0.f; }

        #pragma unroll 2
        for (int k0 = 0; k0 < 768; k0 += 4) {
            float a[4][4];
            #pragma unroll
            for (int mi = 0; mi < 4; mi++) {
                float4 t = *(const float4*)&buf[(r0 + mi) * 768 + k0];
                a[mi][0] = t.x; a[mi][1] = t.y; a[mi][2] = t.z; a[mi][3] = t.w;
            }
            #pragma unroll
            for (int kk = 0; kk < 4; kk++) {
                float4 bk = __ldg((const float4*)&Wk[(k0 + kk) * 128 + nb]);
                float4 bv = __ldg((const float4*)&Wv[(k0 + kk) * 128 + nb]);
                #pragma unroll
                for (int mi = 0; mi < 4; mi++) {
                    float am = a[mi][kk];
                    ak[mi][0] = fmaf(am, bk.x, ak[mi][0]);
                    ak[mi][1] = fmaf(am, bk.y, ak[mi][1]);
                    ak[mi][2] = fmaf(am, bk.z, ak[mi][2]);
                    ak[mi][3] = fmaf(am, bk.w, ak[mi][3]);
                    av[mi][0] = fmaf(am, bv.x, av[mi][0]);
                    av[mi][1] = fmaf(am, bv.y, av[mi][1]);
                    av[mi][2] = fmaf(am, bv.z, av[mi][2]);
                    av[mi][3] = fmaf(am, bv.w, av[mi][3]);
                }
            }
        }
        // sigmoid(k) . q  -> reduce over the 8 lanes of this head group
        #pragma unroll
        for (int mi = 0; mi < 4; mi++) {
            float p = 0.f;
            #pragma unroll
            for (int ci = 0; ci < 4; ci++) {
                float kv = 1.f / (1.f + __expf(-ak[mi][ci]));
                p = fmaf(kv, Qs[(r0 + mi) * 128 + nb + ci], p);
            }
            p += __shfl_xor_sync(0xffffffffu, p, 4);
            p += __shfl_xor_sync(0xffffffffu, p, 2);
            p += __shfl_xor_sync(0xffffffffu, p, 1);
            if ((tn & 7) == 0) s_sm[(r0 + mi) * 4 + h] = p;
        }
        __syncthreads();
        #pragma unroll
        for (int mi = 0; mi < 4; mi++) {
            const float s = s_sm[(r0 + mi) * 4 + h];
            float4 t;
            t.x = s * av[mi][0]; t.y = s * av[mi][1];
            t.z = s * av[mi][2]; t.w = s * av[mi][3];
            *(float4*)&OUTs[(r0 + mi) * 128 + nb] = t;
        }
    }
    __syncthreads();  // OUTs done; ctx in buf now dead

    // -------- Phase C: y = OUT @ Wo + bo  (512 cols in 4 passes), row sumsq --------
    float ss[4] = {0.f, 0.f, 0.f, 0.f};
    float* ybuf = buf;  // reuse (32x512)
    #pragma unroll 1
    for (int pass = 0; pass < 4; pass++) {
        const int nc = pass * 128 + nb;
        float4 b0 = __ldg((const float4*)&bo[nc]);
        float acc[4][4];
        #pragma unroll
        for (int mi = 0; mi < 4; mi++) {
            acc[mi][0] = b0.x; acc[mi][1] = b0.y; acc[mi][2] = b0.z; acc[mi][3] = b0.w;
        }
        #pragma unroll 2
        for (int k0 = 0; k0 < 128; k0 += 4) {
            float a[4][4];
            #pragma unroll
            for (int mi = 0; mi < 4; mi++) {
                float4 t = *(const float4*)&OUTs[(r0 + mi) * 128 + k0];
                a[mi][0] = t.x; a[mi][1] = t.y; a[mi][2] = t.z; a[mi][3] = t.w;
            }
            #pragma unroll
            for (int kk = 0; kk < 4; kk++) {
                float4 b = __ldg((const float4*)&Wo[(k0 + kk) * 512 + nc]);
                #pragma unroll
                for (int mi = 0; mi < 4; mi++) {
                    float am = a[mi][kk];
                    acc[mi][0] = fmaf(am, b.x, acc[mi][0]);
                    acc[mi][1] = fmaf(am, b.y, acc[mi][1]);
                    acc[mi][2] = fmaf(am, b.z, acc[mi][2]);
                    acc[mi][3] = fmaf(am, b.w, acc[mi][3]);
                }
            }
        }
        #pragma unroll
        for (int mi = 0; mi < 4; mi++) {
            float4 t;
            t.x = acc[mi][0]; t.y = acc[mi][1]; t.z = acc[mi][2]; t.w = acc[mi][3];
            *(float4*)&ybuf[(r0 + mi) * 512 + nc] = t;
            ss[mi] += acc[mi][0] * acc[mi][0] + acc[mi][1] * acc[mi][1]
                    + acc[mi][2] * acc[mi][2] + acc[mi][3] * acc[mi][3];
        }
    }
    // row sumsq: reduce across the 32 lanes (all lanes of a warp share the same 4 rows)
    #pragma unroll
    for (int mi = 0; mi < 4; mi++) {
        float v = ss[mi];
        v += __shfl_xor_sync(0xffffffffu, v, 16);
        v += __shfl_xor_sync(0xffffffffu, v, 8);
        v += __shfl_xor_sync(0xffffffffu, v, 4);
        v += __shfl_xor_sync(0xffffffffu, v, 2);
        v += __shfl_xor_sync(0xffffffffu, v, 1);
        if (tn == 0) norm2[r0 + mi] = v;
    }
    __syncthreads();
    if (tid < 32)
        rsc[tid] = 22.627416997969522f / fmaxf(sqrtf(norm2[tid]), 1e-12f);  // sqrt(512)/max(norm,eps)
    __syncthreads();

    // ---------------- write out: y * rsc[row] * g[col] ----------------
    {
        float4* og = (float4*)(out + Rbase * 512);
        const float4* gg = (const float4*)g;
        const float4* yb = (const float4*)ybuf;
        for (int i = tid; i < 32 * 128; i += THREADS) {
            const int m  = i >> 7;
            const int n4 = i & 127;
            float4 v  = yb[i];
            float4 gv = __ldg(&gg[n4]);
            const float sc = rsc[m];
            v.x *= sc * gv.x; v.y *= sc * gv.y; v.z *= sc * gv.z; v.w *= sc * gv.w;
            og[i] = v;
        }
    }
}

extern "C" void kernel_launch(void* const* d_in, const int* in_sizes, int n_in,
                              void* d_out, int out_size)
{
    const float* x   = (const float*)d_in[0];
    const float* ctx = (const float*)d_in[1];
    const float* Wq  = (const float*)d_in[2];
    const float* Wk  = (const float*)d_in[3];
    const float* Wv  = (const float*)d_in[4];
    const float* Wo  = (const float*)d_in[5];
    const float* bo  = (const float*)d_in[6];
    const float* g   = (const float*)d_in[7];
    float* out = (float*)d_out;

    const int B = in_sizes[0] / 512;           // 65536
    const size_t SMEM = (size_t)(32 * 768 + 32 * 128 + 32 * 128 + 128 + 32 + 32) * sizeof(float);

    cudaFuncSetAttribute(lca_fused, cudaFuncAttributeMaxDynamicSharedMemorySize, (int)SMEM);
    lca_fused<<<B / 32, THREADS, SMEM>>>(x, ctx, Wq, Wk, Wv, Wo, bo, g, out);
}

// round 2
// speedup vs baseline: 3.5132x; 3.5132x over previous
#include <cuda_runtime.h>
#include <math.h>

#define THREADS 256
#define ROWS 128
#define KC 32
#define LDA 36      // activation/weight smem ld for K-chunks (32+4): 36 % 32 == 4 -> conflict-free frags
#define LDP 132     // P / Qs / Wo_t smem ld (128+4): 132 % 32 == 4

// smem float offsets
#define OFF_ACT 0            // 2 * 128*36 = 9216   (x / ctx chunk, double buffered)
#define OFF_WK  9216         // 2 * 128*36 = 9216   (Wq_t phase A; Wk_t phase B)
#define OFF_WV  18432        // 2 * 128*36 = 9216   (Wv_t phase B)
#define OFF_QS  27648        // 128*132 = 16896     (Qs, later P — same rows, overwritten after s)
#define OFF_WO  0            // phase C Wo_t [128][132] = 16896 (reuses ACT+WK region)
#define SMEM_FLOATS 44544    // 178176 bytes

__device__ __forceinline__ unsigned tf32_bits(float x) {
    unsigned u; asm("cvt.rna.tf32.f32 %0, %1;" : "=r"(u) : "f"(x)); return u;
}
__device__ __forceinline__ float tf32f(float x) { return __uint_as_float(tf32_bits(x)); }

__device__ __forceinline__ void mma8(float* d, unsigned a0, unsigned a1, unsigned a2, unsigned a3,
                                     unsigned b0, unsigned b1) {
    asm volatile(
        "mma.sync.aligned.m16n8k8.row.col.f32.tf32.tf32.f32 "
        "{%0,%1,%2,%3},{%4,%5,%6,%7},{%8,%9},{%0,%1,%2,%3};"
        : "+f"(d[0]), "+f"(d[1]), "+f"(d[2]), "+f"(d[3])
        : "r"(a0), "r"(a1), "r"(a2), "r"(a3), "r"(b0), "r"(b1));
}

#define CP_COMMIT() asm volatile("cp.async.commit_group;")
#define CP_WAIT(n)  asm volatile("cp.async.wait_group %0;" :: "n"(n))

// activations: 128 rows x 32 cols chunk -> smem [r*LDA + c], via cp.async 16B
__device__ __forceinline__ void act_cp(float* sm, int dstBase, const float* A,
                                       size_t rowBase, int gld, int kb, int tid) {
#pragma unroll
    for (int i = 0; i < 4; i++) {
        int idx = tid + THREADS * i;         // 0..1023
        int r = idx >> 3, q = (idx & 7) * 4;
        unsigned sa = (unsigned)__cvta_generic_to_shared(&sm[dstBase + r * LDA + q]);
        const float* gp = A + (rowBase + r) * (size_t)gld + kb + q;
        asm volatile("cp.async.cg.shared.global [%0], [%1], 16;" :: "r"(sa), "l"(gp));
    }
}

// weights [K,128] row-major: prefetch 32 scalars? (16 per matrix) for a 32-k chunk
__device__ __forceinline__ void w_ldg(const float* W, int kb, int n, int kq, float r[16]) {
#pragma unroll
    for (int it = 0; it < 4; it++) {
        int k4 = it * 8 + kq * 4;
        const float* gp = W + (size_t)(kb + k4) * 128 + n;
        r[it * 4 + 0] = __ldg(gp);
        r[it * 4 + 1] = __ldg(gp + 128);
        r[it * 4 + 2] = __ldg(gp + 256);
        r[it * 4 + 3] = __ldg(gp + 384);
    }
}
__device__ __forceinline__ void w_sts(float* sm, int dst, int n, int kq, const float r[16]) {
#pragma unroll
    for (int it = 0; it < 4; it++) {
        int k4 = it * 8 + kq * 4;
        float4 v;
        v.x = tf32f(r[it * 4 + 0]); v.y = tf32f(r[it * 4 + 1]);
        v.z = tf32f(r[it * 4 + 2]); v.w = tf32f(r[it * 4 + 3]);
        *(float4*)&sm[dst + n * LDA + k4] = v;
    }
}

__global__ void __launch_bounds__(THREADS, 1)
lca_tc(const float* __restrict__ x,  const float* __restrict__ ctx,
       const float* __restrict__ Wq, const float* __restrict__ Wk,
       const float* __restrict__ Wv, const float* __restrict__ Wo,
       const float* __restrict__ bo, float* __restrict__ out)
{
    extern __shared__ float sm[];
    const int tid  = threadIdx.x;
    const int lane = tid & 31;
    const int warp = tid >> 5;
    const int wr   = warp * 16;          // warp's row band
    const int l4   = lane >> 2;          // 0..7
    const int lm   = lane & 3;           // 0..3
    const int wn   = tid & 127;          // staging: weight column
    const int wkq  = tid >> 7;           // staging: 0/1
    const size_t Rbase = (size_t)blockIdx.x * ROWS;

    // ======================= Phase A: Q = x @ Wq =======================
    {
        float qa[16][4];
#pragma unroll
        for (int t = 0; t < 16; t++)
#pragma unroll
            for (int j = 0; j < 4; j++) qa[t][j] = 0.f;

        // prologue: chunk 0
        {
            float wr0[16];
            w_ldg(Wq, 0, wn, wkq, wr0);
            w_sts(sm, OFF_WK, wn, wkq, wr0);
            act_cp(sm, OFF_ACT, x, Rbase, 512, 0, tid);
            CP_COMMIT();
        }
        const int NC = 512 / KC;  // 16
        for (int c = 0; c < NC; c++) {
            const int cb = c & 1;
            float wreg[16];
            if (c + 1 < NC) {
                w_ldg(Wq, (c + 1) * KC, wn, wkq, wreg);
                act_cp(sm, OFF_ACT + ((c + 1) & 1) * 4608, x, Rbase, 512, (c + 1) * KC, tid);
                CP_COMMIT();
                CP_WAIT(1);
            } else {
                CP_WAIT(0);
            }
            __syncthreads();
            const int XB = OFF_ACT + cb * 4608;
            const int WB = OFF_WK + cb * 4608;
#pragma unroll
            for (int ks = 0; ks < 4; ks++) {
                const int k0 = ks * 8;
                const float* Xp = &sm[XB + (wr + l4) * LDA + k0 + lm];
                unsigned a0 = tf32_bits(Xp[0]);
                unsigned a1 = tf32_bits(Xp[8 * LDA]);
                unsigned a2 = tf32_bits(Xp[4]);
                unsigned a3 = tf32_bits(Xp[8 * LDA + 4]);
#pragma unroll
                for (int t = 0; t < 16; t++) {
                    const float* Bp = &sm[WB + (8 * t + l4) * LDA + k0 + lm];
                    mma8(qa[t], a0, a1, a2, a3,
                         __float_as_uint(Bp[0]), __float_as_uint(Bp[4]));
                }
            }
            if (c + 1 < NC) w_sts(sm, OFF_WK + ((c + 1) & 1) * 4608, wn, wkq, wreg);
            __syncthreads();
        }
        // epilogue: acc -> Qs
#pragma unroll
        for (int t = 0; t < 16; t++) {
            const int c0 = 8 * t + 2 * lm;
            *(float2*)&sm[OFF_QS + (wr + l4) * LDP + c0]       = make_float2(qa[t][0], qa[t][1]);
            *(float2*)&sm[OFF_QS + (wr + l4 + 8) * LDP + c0]   = make_float2(qa[t][2], qa[t][3]);
        }
    }
    __syncthreads();

    // ================= softmax per (row, head), *scale =================
    for (int task = tid; task < ROWS * 4; task += THREADS) {
        const int r = task >> 2, h = task & 3;
        float* qp = &sm[OFF_QS + r * LDP + h * 32];
        float mx = qp[0];
#pragma unroll
        for (int i = 1; i < 32; i++) mx = fmaxf(mx, qp[i]);
        float s = 0.f;
#pragma unroll
        for (int i = 0; i < 32; i++) s += __expf(qp[i] - mx);
        const float inv = 0.17677669529663687f / s;  // 32^-0.5 / sum
#pragma unroll
        for (int i = 0; i < 32; i++) qp[i] = __expf(qp[i] - mx) * inv;
    }
    __syncthreads();

    // ===== Phase B: k=sigmoid(ctx@Wk), v=ctx@Wv, s=k.q, P=s*v =====
    {
        float ka[16][4], va[16][4];
#pragma unroll
        for (int t = 0; t < 16; t++)
#pragma unroll
            for (int j = 0; j < 4; j++) { ka[t][j] = 0.f; va[t][j] = 0.f; }

        {
            float wr0[16], wr1[16];
            w_ldg(Wk, 0, wn, wkq, wr0);
            w_ldg(Wv, 0, wn, wkq, wr1);
            w_sts(sm, OFF_WK, wn, wkq, wr0);
            w_sts(sm, OFF_WV, wn, wkq, wr1);
            act_cp(sm, OFF_ACT, ctx, Rbase, 768, 0, tid);
            CP_COMMIT();
        }
        const int NC = 768 / KC;  // 24
        for (int c = 0; c < NC; c++) {
            const int cb = c & 1;
            float wkr[16], wvr[16];
            if (c + 1 < NC) {
                w_ldg(Wk, (c + 1) * KC, wn, wkq, wkr);
                w_ldg(Wv, (c + 1) * KC, wn, wkq, wvr);
                act_cp(sm, OFF_ACT + ((c + 1) & 1) * 4608, ctx, Rbase, 768, (c + 1) * KC, tid);
                CP_COMMIT();
                CP_WAIT(1);
            } else {
                CP_WAIT(0);
            }
            __syncthreads();
            const int XB = OFF_ACT + cb * 4608;
            const int KB = OFF_WK + cb * 4608;
            const int VB = OFF_WV + cb * 4608;
#pragma unroll
            for (int ks = 0; ks < 4; ks++) {
                const int k0 = ks * 8;
                const float* Xp = &sm[XB + (wr + l4) * LDA + k0 + lm];
                unsigned a0 = tf32_bits(Xp[0]);
                unsigned a1 = tf32_bits(Xp[8 * LDA]);
                unsigned a2 = tf32_bits(Xp[4]);
                unsigned a3 = tf32_bits(Xp[8 * LDA + 4]);
#pragma unroll
                for (int t = 0; t < 16; t++) {
                    const float* Kp = &sm[KB + (8 * t + l4) * LDA + k0 + lm];
                    mma8(ka[t], a0, a1, a2, a3,
                         __float_as_uint(Kp[0]), __float_as_uint(Kp[4]));
                    const float* Vp = &sm[VB + (8 * t + l4) * LDA + k0 + lm];
                    mma8(va[t], a0, a1, a2, a3,
                         __float_as_uint(Vp[0]), __float_as_uint(Vp[4]));
                }
            }
            if (c + 1 < NC) {
                w_sts(sm, OFF_WK + ((c + 1) & 1) * 4608, wn, wkq, wkr);
                w_sts(sm, OFF_WV + ((c + 1) & 1) * 4608, wn, wkq, wvr);
            }
            __syncthreads();
        }

        // epilogue: s[h] = sum_d sigmoid(k)*q ; P = s*v  (rows are warp-private)
        float s1[4], s2[4];
#pragma unroll
        for (int h = 0; h < 4; h++) {
            float p1 = 0.f, p2 = 0.f;
#pragma unroll
            for (int tt = 0; tt < 4; tt++) {
                const int t = 4 * h + tt;
                const int c0 = 8 * t + 2 * lm;
                const float* q1 = &sm[OFF_QS + (wr + l4) * LDP + c0];
                const float* q2 = &sm[OFF_QS + (wr + l4 + 8) * LDP + c0];
                p1 += q1[0] / (1.f + __expf(-ka[t][0])) + q1[1] / (1.f + __expf(-ka[t][1]));
                p2 += q2[0] / (1.f + __expf(-ka[t][2])) + q2[1] / (1.f + __expf(-ka[t][3]));
            }
            p1 += __shfl_xor_sync(0xffffffffu, p1, 1);
            p1 += __shfl_xor_sync(0xffffffffu, p1, 2);
            p2 += __shfl_xor_sync(0xffffffffu, p2, 1);
            p2 += __shfl_xor_sync(0xffffffffu, p2, 2);
            s1[h] = p1; s2[h] = p2;
        }
        // all reads of Q for this warp's rows are done; overwrite with P (tf32)
#pragma unroll
        for (int t = 0; t < 16; t++) {
            const int h = t >> 2;
            const int c0 = 8 * t + 2 * lm;
            *(float2*)&sm[OFF_QS + (wr + l4) * LDP + c0] =
                make_float2(tf32f(s1[h] * va[t][0]), tf32f(s1[h] * va[t][1]));
            *(float2*)&sm[OFF_QS + (wr + l4 + 8) * LDP + c0] =
                make_float2(tf32f(s2[h] * va[t][2]), tf32f(s2[h] * va[t][3]));
        }
        __syncwarp();
    }

    // ============ Phase C: y = P @ Wo + bo (4 passes of 128 cols) ============
    for (int p = 0; p < 4; p++) {
        __syncthreads();  // previous pass done reading Wo_t / P writes visible
        // stage Wo_t pass p: [128 n][128 k] transposed, tf32
        {
            const int pc = p * 128;
#pragma unroll 4
            for (int it = 0; it < 16; it++) {
                const int k4 = it * 8 + wkq * 4;
                const float* gp = Wo + (size_t)k4 * 512 + pc + wn;
                float4 v;
                v.x = tf32f(__ldg(gp));
                v.y = tf32f(__ldg(gp + 512));
                v.z = tf32f(__ldg(gp + 1024));
                v.w = tf32f(__ldg(gp + 1536));
                *(float4*)&sm[OFF_WO + wn * LDP + k4] = v;
            }
        }
        __syncthreads();

        float ya[16][4];
#pragma unroll
        for (int t = 0; t < 16; t++)
#pragma unroll
            for (int j = 0; j < 4; j++) ya[t][j] = 0.f;

#pragma unroll
        for (int ks = 0; ks < 16; ks++) {
            const int k0 = ks * 8;
            const float* Pp = &sm[OFF_QS + (wr + l4) * LDP + k0 + lm];
            unsigned a0 = __float_as_uint(Pp[0]);
            unsigned a1 = __float_as_uint(Pp[8 * LDP]);
            unsigned a2 = __float_as_uint(Pp[4]);
            unsigned a3 = __float_as_uint(Pp[8 * LDP + 4]);
#pragma unroll
            for (int t = 0; t < 16; t++) {
                const float* Bp = &sm[OFF_WO + (8 * t + l4) * LDP + k0 + lm];
                mma8(ya[t], a0, a1, a2, a3,
                     __float_as_uint(Bp[0]), __float_as_uint(Bp[4]));
            }
        }
        // epilogue: +bo, direct STG (normalization done by second kernel)
        const int pc = p * 128;
#pragma unroll
        for (int t = 0; t < 16; t++) {
            const int col = pc + 8 * t + 2 * lm;
            const float b0v = __ldg(&bo[col]), b1v = __ldg(&bo[col + 1]);
            *(float2*)&out[(Rbase + wr + l4) * 512 + col] =
                make_float2(ya[t][0] + b0v, ya[t][1] + b1v);
            *(float2*)&out[(Rbase + wr + l4 + 8) * 512 + col] =
                make_float2(ya[t][2] + b0v, ya[t][3] + b1v);
        }
    }
}

// in-place RMS normalize: y = y / max(||y||,1e-12) * g * sqrt(512)
__global__ void __launch_bounds__(256)
lca_norm(float* __restrict__ out, const float* __restrict__ g)
{
    const int warp = threadIdx.x >> 5, lane = threadIdx.x & 31;
    const size_t r = (size_t)blockIdx.x * 8 + warp;
    float* yp = out + r * 512;

    float4 v[4];
    float ss = 0.f;
#pragma unroll
    for (int i = 0; i < 4; i++) {
        v[i] = *(float4*)&yp[(i * 32 + lane) * 4];
        ss += v[i].x * v[i].x + v[i].y * v[i].y + v[i].z * v[i].z + v[i].w * v[i].w;
    }
    ss += __shfl_xor_sync(0xffffffffu, ss, 16);
    ss += __shfl_xor_sync(0xffffffffu, ss, 8);
    ss += __shfl_xor_sync(0xffffffffu, ss, 4);
    ss += __shfl_xor_sync(0xffffffffu, ss, 2);
    ss += __shfl_xor_sync(0xffffffffu, ss, 1);
    const float rsc = 22.627416997969522f / fmaxf(sqrtf(ss), 1e-12f);
#pragma unroll
    for (int i = 0; i < 4; i++) {
        float4 gv = __ldg((const float4*)&g[(i * 32 + lane) * 4]);
        v[i].x *= rsc * gv.x; v[i].y *= rsc * gv.y;
        v[i].z *= rsc * gv.z; v[i].w *= rsc * gv.w;
        *(float4*)&yp[(i * 32 + lane) * 4] = v[i];
    }
}

extern "C" void kernel_launch(void* const* d_in, const int* in_sizes, int n_in,
                              void* d_out, int out_size)
{
    const float* x   = (const float*)d_in[0];
    const float* ctx = (const float*)d_in[1];
    const float* Wq  = (const float*)d_in[2];
    const float* Wk  = (const float*)d_in[3];
    const float* Wv  = (const float*)d_in[4];
    const float* Wo  = (const float*)d_in[5];
    const float* bo  = (const float*)d_in[6];
    const float* g   = (const float*)d_in[7];
    float* out = (float*)d_out;

    const int B = in_sizes[0] / 512;  // 65536
    const size_t SMEM = (size_t)SMEM_FLOATS * sizeof(float);

    cudaFuncSetAttribute(lca_tc, cudaFuncAttributeMaxDynamicSharedMemorySize, (int)SMEM);
    lca_tc<<<B / ROWS, THREADS, SMEM>>>(x, ctx, Wq, Wk, Wv, Wo, bo, out);
    lca_norm<<<B / 8, 256>>>(out, g);
}